// round 14
// baseline (speedup 1.0000x reference)
#include <cuda_runtime.h>
#include <cuda_fp16.h>
#include <cstdint>

#define SS 4096
#define DK 64
#define DM 512
#define HH 8
#define BB 2
#define BH 16

// Scratch (static device globals — no runtime allocation)
__device__ __half g_Xh[BB*SS*DM];    // x converted to fp16 [m][k]
__device__ __half g_WT[4*DM*DM];     // Wq,Wk,Wv,Wo transposed to [n][k] fp16
__device__ __half g_Qh[BH*SS*DK];    // [bh][s][d], pre-scaled by log2(e)/8
__device__ __half g_Kh[BH*SS*DK];    // [bh][s][d]
__device__ __half g_Vh[BH*SS*DK];    // [bh][d][s]  (transposed for B-frag loads)
__device__ __half g_Oh[BB*SS*DM];    // attention output fp16 (concat layout)

__device__ __forceinline__ uint32_t pack_half2(float lo, float hi) {
    uint32_t u; asm("cvt.rn.f16x2.f32 %0, %1, %2;" : "=r"(u) : "f"(hi), "f"(lo)); return u;
}
__device__ __forceinline__ uint32_t ex2h2(uint32_t x) {
    uint32_t y; asm("ex2.approx.f16x2 %0, %1;" : "=r"(y) : "r"(x)); return y;
}
__device__ __forceinline__ uint32_t hadd2(uint32_t a, uint32_t b) {
    uint32_t y; asm("add.f16x2 %0, %1, %2;" : "=r"(y) : "r"(a), "r"(b)); return y;
}
// fp16: D += A(16x16) * B(16x8), f32 accum
__device__ __forceinline__ void mma16(float* d, const uint32_t* a, const uint32_t* b) {
    asm volatile("mma.sync.aligned.m16n8k16.row.col.f32.f16.f16.f32 "
        "{%0,%1,%2,%3}, {%4,%5,%6,%7}, {%8,%9}, {%0,%1,%2,%3};"
        : "+f"(d[0]), "+f"(d[1]), "+f"(d[2]), "+f"(d[3])
        : "r"(a[0]), "r"(a[1]), "r"(a[2]), "r"(a[3]), "r"(b[0]), "r"(b[1]));
}
__device__ __forceinline__ void cpa16(uint32_t dst, const void* src) {
    asm volatile("cp.async.cg.shared.global [%0], [%1], 16;" :: "r"(dst), "l"(src));
}
// 4x m8n8 b16 matrices -> mma B fragments
__device__ __forceinline__ void ldsm4(uint32_t& r0, uint32_t& r1, uint32_t& r2, uint32_t& r3,
                                      uint32_t addr) {
    asm volatile("ldmatrix.sync.aligned.m8n8.x4.shared.b16 {%0,%1,%2,%3}, [%4];"
        : "=r"(r0), "=r"(r1), "=r"(r2), "=r"(r3) : "r"(addr));
}

// ================= converters =================
__global__ __launch_bounds__(256) void convx_kernel(const float* __restrict__ X) {
    size_t i = ((size_t)blockIdx.x*256 + threadIdx.x) * 8;
    float4 v0 = *(const float4*)(X + i);
    float4 v1 = *(const float4*)(X + i + 4);
    uint4 p;
    p.x = pack_half2(v0.x, v0.y); p.y = pack_half2(v0.z, v0.w);
    p.z = pack_half2(v1.x, v1.y); p.w = pack_half2(v1.z, v1.w);
    *(uint4*)(g_Xh + i) = p;
}

// transpose+convert weights: g_WT[w][n][k] = W_w[k][n]
__global__ __launch_bounds__(256) void convw_kernel(const float* __restrict__ Wq,
                                                    const float* __restrict__ Wk,
                                                    const float* __restrict__ Wv,
                                                    const float* __restrict__ Wo) {
    __shared__ float t[32][33];
    const int w = blockIdx.z;
    const float* W = (w==0) ? Wq : (w==1) ? Wk : (w==2) ? Wv : Wo;
    __half* out = g_WT + (size_t)w*DM*DM;
    const int tx = threadIdx.x & 31, ty = threadIdx.x >> 5;
    const int bx = blockIdx.x * 32, by = blockIdx.y * 32;
    #pragma unroll
    for (int j = 0; j < 32; j += 8)
        t[ty+j][tx] = W[(size_t)(by+ty+j)*DM + bx+tx];
    __syncthreads();
    #pragma unroll
    for (int j = 0; j < 32; j += 8)
        out[(size_t)(bx+ty+j)*DM + by+tx] = __float2half_rn(t[tx][ty+j]);
}

// ================= fp16 GEMM: 128x128x32, 3-stage cp.async, 8 warps x (64x32) ===========
#define GBM 128
#define GBN 128
#define GBK 32
#define GAST 40
#define STG_A (GBM*GAST)
#define STG_H ((GBM+GBN)*GAST)
#define GSM_TOTAL (3*STG_H)           // 61440 bytes

// mode: -1 => qkv from g_Xh; 3 => oproj from g_Oh -> Out (fp32)
__global__ __launch_bounds__(256) void gemm16_kernel(float* __restrict__ Out, int mode)
{
    extern __shared__ __half gsm[];
    const int tid = threadIdx.x;
    const int warp = tid >> 5, lane = tid & 31;
    const int g = lane >> 2, c = lane & 3;
    const int wm = (warp & 1) * 64, wn = (warp >> 1) * 32;
    const int mb = blockIdx.y;

    int proj, cb;
    const __half* A;
    if (mode < 0) { proj = blockIdx.x >> 2; cb = (blockIdx.x & 3) * GBN; A = g_Xh; }
    else          { proj = 3;               cb = blockIdx.x * GBN;       A = g_Oh; }
    const __half* Bp = g_WT + (size_t)proj*DM*DM;

    float acc[4][4][4];
    #pragma unroll
    for (int i=0;i<4;i++)
        #pragma unroll
        for (int j=0;j<4;j++)
            #pragma unroll
            for (int k=0;k<4;k++) acc[i][j][k] = 0.f;

    uint32_t sb = (uint32_t)__cvta_generic_to_shared(gsm);
    const int ar = tid >> 1;
    const int ac = (tid & 1) * 2;

    const __half* Ag = A  + (size_t)(mb*GBM + ar)*DM;
    const __half* Bg = Bp + (size_t)(cb + ar)*DM;

    auto issue = [&](int slab, int stg) {
        uint32_t ab = sb + (uint32_t)(stg*STG_H)*2;
        uint32_t bb = ab + (uint32_t)STG_A*2;
        int k0 = slab * GBK;
        #pragma unroll
        for (int i = 0; i < 2; i++) {
            int ch = ac + i;
            cpa16(ab + (uint32_t)(ar*GAST + ch*8)*2, Ag + k0 + ch*8);
            cpa16(bb + (uint32_t)(ar*GAST + ch*8)*2, Bg + k0 + ch*8);
        }
        asm volatile("cp.async.commit_group;" ::: "memory");
    };

    issue(0, 0);
    issue(1, 1);

    const int NSLAB = DM / GBK;
    for (int slab = 0; slab < NSLAB; slab++) {
        const int stg = slab % 3;
        if (slab + 2 < NSLAB) {
            issue(slab + 2, (slab + 2) % 3);
            asm volatile("cp.async.wait_group 2;" ::: "memory");
        } else if (slab + 1 < NSLAB) {
            asm volatile("cp.async.wait_group 1;" ::: "memory");
        } else {
            asm volatile("cp.async.wait_group 0;" ::: "memory");
        }
        __syncthreads();

        const __half* As_ = gsm + stg*STG_H;
        const __half* Bs_ = As_ + STG_A;

        #pragma unroll
        for (int ks = 0; ks < 2; ks++) {
            uint32_t a[4][4];
            #pragma unroll
            for (int mi = 0; mi < 4; mi++) {
                const __half* ap = As_ + (wm + mi*16 + g)*GAST + ks*16 + 2*c;
                a[mi][0] = *(const uint32_t*)(ap);
                a[mi][1] = *(const uint32_t*)(ap + 8*GAST);
                a[mi][2] = *(const uint32_t*)(ap + 8);
                a[mi][3] = *(const uint32_t*)(ap + 8*GAST + 8);
            }
            #pragma unroll
            for (int ni = 0; ni < 4; ni++) {
                uint32_t b[2];
                const __half* bp = Bs_ + (wn + ni*8 + g)*GAST + ks*16 + 2*c;
                b[0] = *(const uint32_t*)(bp);
                b[1] = *(const uint32_t*)(bp + 8);
                #pragma unroll
                for (int mi = 0; mi < 4; mi++) mma16(acc[mi][ni], a[mi], b);
            }
        }
        __syncthreads();
    }

    if (proj == 3) {
        #pragma unroll
        for (int mi = 0; mi < 4; mi++)
            #pragma unroll
            for (int h = 0; h < 2; h++) {
                int gm = mb*GBM + wm + mi*16 + g + h*8;
                #pragma unroll
                for (int ni = 0; ni < 4; ni++) {
                    float2 v = { acc[mi][ni][h*2+0], acc[mi][ni][h*2+1] };
                    *(float2*)(Out + (size_t)gm*DM + cb + wn + ni*8 + 2*c) = v;
                }
            }
    } else {
        const float qscale = (proj == 0) ? 0.125f * 1.44269504088896f : 1.0f;
        #pragma unroll
        for (int mi = 0; mi < 4; mi++)
            #pragma unroll
            for (int h = 0; h < 2; h++) {
                int gm = mb*GBM + wm + mi*16 + g + h*8;
                int b = gm >> 12, s = gm & (SS-1);
                #pragma unroll
                for (int ni = 0; ni < 4; ni++) {
                    int wc = cb + wn + ni*8 + 2*c;
                    int hd = wc >> 6, d = wc & 63;
                    float v0 = acc[mi][ni][h*2+0];
                    float v1 = acc[mi][ni][h*2+1];
                    if (proj == 2) {
                        __half* o = g_Vh + ((size_t)(b*HH + hd)*DK + d)*SS + s;
                        o[0]  = __float2half_rn(v0);
                        o[SS] = __float2half_rn(v1);
                    } else {
                        __half* OutB = (proj == 0) ? g_Qh : g_Kh;
                        *(uint32_t*)(OutB + (((size_t)(b*HH + hd)*SS) + s)*DK + d)
                            = pack_half2(v0*qscale, v1*qscale);
                    }
                }
            }
    }
}

// ===== Flash attention v8: 4 warps x 32 rows (2x B-frag reuse), pipelined, triple buffer ===
#define KSTH 72                  // row stride in halves -> ldsm rows on banks 4r, conflict-free
#define TILE_H (64*KSTH)         // 4608 halves per buffer
#define SMH_TOTAL (6*TILE_H)     // 27648 halves = 55296 bytes
#define NKT (SS/64)              // 64 key tiles

__global__ __launch_bounds__(128, 2) void attn_kernel()
{
    extern __shared__ __half smh[];
    const int tid = threadIdx.x;
    const int warp = tid >> 5, lane = tid & 31;
    const int g = lane >> 2, c = lane & 3;
    const int wm = warp * 32;    // 4 warps x 32 q-rows
    const int qt = blockIdx.x;   // 0..31
    const int bh = blockIdx.y;   // 0..15

    const __half* Qg = g_Qh + ((size_t)bh*SS + qt*128)*DK;
    const __half* Kg = g_Kh + (size_t)bh*SS*DK;
    const __half* Vg = g_Vh + (size_t)bh*DK*SS;

    // stage Q (128x64) through smem (first 2 buffers), pull A-fragments into registers
    #pragma unroll
    for (int i = 0; i < 8; i++) {
        int e = tid + i*128;
        int row = e >> 3, ch = e & 7;
        *(uint4*)(smh + row*KSTH + ch*8) = *(const uint4*)(Qg + (size_t)row*DK + ch*8);
    }
    __syncthreads();
    uint32_t q[2][4][4];
    #pragma unroll
    for (int mi = 0; mi < 2; mi++)
        #pragma unroll
        for (int t = 0; t < 4; t++) {
            int r0 = wm + mi*16 + g;
            q[mi][t][0] = *(const uint32_t*)(smh + r0*KSTH     + t*16 + 2*c);
            q[mi][t][1] = *(const uint32_t*)(smh + (r0+8)*KSTH + t*16 + 2*c);
            q[mi][t][2] = *(const uint32_t*)(smh + r0*KSTH     + t*16 + 2*c + 8);
            q[mi][t][3] = *(const uint32_t*)(smh + (r0+8)*KSTH + t*16 + 2*c + 8);
        }
    __syncthreads();

    uint32_t sb = (uint32_t)__cvta_generic_to_shared(smh);
    const int l_row = tid >> 1, l_chb = (tid & 1) * 4;   // 64 rows x 8 chunks, 4 per thread

    // per-lane ldmatrix base offset (bytes)
    const uint32_t lmb = (uint32_t)((((lane >> 4) * 8 + (lane & 7)) * KSTH
                                    + ((lane >> 3) & 1) * 8) * 2);

    auto issue = [&](int kt) {
        uint32_t kdst = sb + (uint32_t)((kt % 3)*TILE_H)*2;
        uint32_t vdst = sb + (uint32_t)((3 + kt % 3)*TILE_H)*2;
        #pragma unroll
        for (int j = 0; j < 4; j++)
            cpa16(kdst + (uint32_t)(l_row*KSTH + (l_chb+j)*8)*2,
                  Kg + (size_t)(kt*64 + l_row)*DK + (l_chb+j)*8);
        #pragma unroll
        for (int j = 0; j < 4; j++)
            cpa16(vdst + (uint32_t)(l_row*KSTH + (l_chb+j)*8)*2,
                  Vg + (size_t)l_row*SS + kt*64 + (l_chb+j)*8);
        asm volatile("cp.async.commit_group;" ::: "memory");
    };

    // prologue: tiles 0 and 1 in flight; compute S(0)
    issue(0);
    issue(1);
    asm volatile("cp.async.wait_group 1;" ::: "memory");
    __syncthreads();

    float o[2][8][4];
    float s[2][8][4];
    float lr[2][2] = {{0.f, 0.f}, {0.f, 0.f}};
    #pragma unroll
    for (int mi=0;mi<2;mi++)
        #pragma unroll
        for (int n=0;n<8;n++)
            #pragma unroll
            for (int k=0;k<4;k++) { o[mi][n][k]=0.f; s[mi][n][k]=0.f; }

    {
        const uint32_t kbase = sb + lmb;   // buffer 0
        #pragma unroll
        for (int t = 0; t < 4; t++)
            #pragma unroll
            for (int j = 0; j < 4; j++) {
                uint32_t b[4];
                ldsm4(b[0], b[1], b[2], b[3], kbase + (uint32_t)((j*16*KSTH + t*16) * 2));
                mma16(s[0][2*j  ], q[0][t], b);
                mma16(s[0][2*j+1], q[0][t], b + 2);
                mma16(s[1][2*j  ], q[1][t], b);
                mma16(s[1][2*j+1], q[1][t], b + 2);
            }
    }
    asm volatile("cp.async.wait_group 0;" ::: "memory");
    __syncthreads();

    // main loop: exp(S_kt) -> [PV(kt) || S(kt+1)] -> wait+barrier
    for (int kt = 0; kt < NKT-1; kt++) {
        uint32_t ph[2][8][2];
        #pragma unroll
        for (int mi = 0; mi < 2; mi++) {
            #pragma unroll
            for (int n = 0; n < 8; n++) {
                ph[mi][n][0] = ex2h2(pack_half2(s[mi][n][0], s[mi][n][1]));
                ph[mi][n][1] = ex2h2(pack_half2(s[mi][n][2], s[mi][n][3]));
            }
            #pragma unroll
            for (int h = 0; h < 2; h++) {
                uint32_t t0 = hadd2(ph[mi][0][h], ph[mi][1][h]);
                uint32_t t1 = hadd2(ph[mi][2][h], ph[mi][3][h]);
                uint32_t t2 = hadd2(ph[mi][4][h], ph[mi][5][h]);
                uint32_t t3 = hadd2(ph[mi][6][h], ph[mi][7][h]);
                uint32_t t4 = hadd2(t0, t1);
                uint32_t t5 = hadd2(t2, t3);
                float2 f0 = __half22float2(*(__half2*)&t4);
                float2 f1 = __half22float2(*(__half2*)&t5);
                lr[mi][h] += (f0.x + f0.y) + (f1.x + f1.y);
            }
            #pragma unroll
            for (int n=0;n<8;n++)
                #pragma unroll
                for (int k=0;k<4;k++) s[mi][n][k] = 0.f;
        }

        if (kt + 2 < NKT) issue(kt + 2);

        const uint32_t vbase = sb + (uint32_t)((3 + kt % 3)*TILE_H)*2 + lmb;
        const uint32_t kbase = sb + (uint32_t)(((kt+1) % 3)*TILE_H)*2 + lmb;

        #pragma unroll
        for (int t = 0; t < 4; t++) {
            uint32_t a0[4], a1[4];
            a0[0] = ph[0][2*t][0]; a0[1] = ph[0][2*t][1];
            a0[2] = ph[0][2*t+1][0]; a0[3] = ph[0][2*t+1][1];
            a1[0] = ph[1][2*t][0]; a1[1] = ph[1][2*t][1];
            a1[2] = ph[1][2*t+1][0]; a1[3] = ph[1][2*t+1][1];
            #pragma unroll
            for (int j = 0; j < 4; j++) {
                uint32_t b[4];
                ldsm4(b[0], b[1], b[2], b[3], vbase + (uint32_t)((j*16*KSTH + t*16) * 2));
                mma16(o[0][2*j  ], a0, b);
                mma16(o[0][2*j+1], a0, b + 2);
                mma16(o[1][2*j  ], a1, b);
                mma16(o[1][2*j+1], a1, b + 2);
            }
            #pragma unroll
            for (int j = 0; j < 4; j++) {
                uint32_t b[4];
                ldsm4(b[0], b[1], b[2], b[3], kbase + (uint32_t)((j*16*KSTH + t*16) * 2));
                mma16(s[0][2*j  ], q[0][t], b);
                mma16(s[0][2*j+1], q[0][t], b + 2);
                mma16(s[1][2*j  ], q[1][t], b);
                mma16(s[1][2*j+1], q[1][t], b + 2);
            }
        }

        asm volatile("cp.async.wait_group 0;" ::: "memory");
        __syncthreads();
    }

    // final tile: exp + PV only
    {
        const int kt = NKT - 1;
        uint32_t ph[2][8][2];
        #pragma unroll
        for (int mi = 0; mi < 2; mi++) {
            #pragma unroll
            for (int n = 0; n < 8; n++) {
                ph[mi][n][0] = ex2h2(pack_half2(s[mi][n][0], s[mi][n][1]));
                ph[mi][n][1] = ex2h2(pack_half2(s[mi][n][2], s[mi][n][3]));
            }
            #pragma unroll
            for (int h = 0; h < 2; h++) {
                uint32_t t0 = hadd2(ph[mi][0][h], ph[mi][1][h]);
                uint32_t t1 = hadd2(ph[mi][2][h], ph[mi][3][h]);
                uint32_t t2 = hadd2(ph[mi][4][h], ph[mi][5][h]);
                uint32_t t3 = hadd2(ph[mi][6][h], ph[mi][7][h]);
                uint32_t t4 = hadd2(t0, t1);
                uint32_t t5 = hadd2(t2, t3);
                float2 f0 = __half22float2(*(__half2*)&t4);
                float2 f1 = __half22float2(*(__half2*)&t5);
                lr[mi][h] += (f0.x + f0.y) + (f1.x + f1.y);
            }
        }
        const uint32_t vbase = sb + (uint32_t)((3 + kt % 3)*TILE_H)*2 + lmb;
        #pragma unroll
        for (int t = 0; t < 4; t++) {
            uint32_t a0[4], a1[4];
            a0[0] = ph[0][2*t][0]; a0[1] = ph[0][2*t][1];
            a0[2] = ph[0][2*t+1][0]; a0[3] = ph[0][2*t+1][1];
            a1[0] = ph[1][2*t][0]; a1[1] = ph[1][2*t][1];
            a1[2] = ph[1][2*t+1][0]; a1[3] = ph[1][2*t+1][1];
            #pragma unroll
            for (int j = 0; j < 4; j++) {
                uint32_t b[4];
                ldsm4(b[0], b[1], b[2], b[3], vbase + (uint32_t)((j*16*KSTH + t*16) * 2));
                mma16(o[0][2*j  ], a0, b);
                mma16(o[0][2*j+1], a0, b + 2);
                mma16(o[1][2*j  ], a1, b);
                mma16(o[1][2*j+1], a1, b + 2);
            }
        }
    }

    // lane-group reduction of row sums
    #pragma unroll
    for (int mi = 0; mi < 2; mi++)
        #pragma unroll
        for (int h = 0; h < 2; h++) {
            lr[mi][h] += __shfl_xor_sync(0xffffffffu, lr[mi][h], 1);
            lr[mi][h] += __shfl_xor_sync(0xffffffffu, lr[mi][h], 2);
        }

    // finalize: normalize, write fp16 concat layout [b][s][h*64+d]
    const int b = bh >> 3, hd = bh & 7;
    #pragma unroll
    for (int mi = 0; mi < 2; mi++)
        #pragma unroll
        for (int h = 0; h < 2; h++) {
            float inv = 1.f / lr[mi][h];
            int row = qt*128 + wm + mi*16 + g + h*8;
            __half* op = g_Oh + ((size_t)(b*SS + row))*DM + hd*DK;
            #pragma unroll
            for (int n=0;n<8;n++)
                *(uint32_t*)(op + n*8 + 2*c) = pack_half2(o[mi][n][h*2]*inv, o[mi][n][h*2+1]*inv);
        }
}

extern "C" void kernel_launch(void* const* d_in, const int* in_sizes, int n_in,
                              void* d_out, int out_size) {
    const float* x  = (const float*)d_in[0];
    const float* Wq = (const float*)d_in[1];
    const float* Wk = (const float*)d_in[2];
    const float* Wv = (const float*)d_in[3];
    const float* Wo = (const float*)d_in[4];
    float* out = (float*)d_out;
    (void)in_sizes; (void)n_in; (void)out_size;

    static const int GEMM_SMEM = GSM_TOTAL * 2;  // 61440 bytes
    static const int ATTN_SMEM = SMH_TOTAL * 2;  // 55296 bytes
    cudaFuncSetAttribute(gemm16_kernel, cudaFuncAttributeMaxDynamicSharedMemorySize, GEMM_SMEM);
    cudaFuncSetAttribute(attn_kernel, cudaFuncAttributeMaxDynamicSharedMemorySize, ATTN_SMEM);

    convx_kernel<<<2048, 256>>>(x);
    convw_kernel<<<dim3(16, 16, 4), 256>>>(Wq, Wk, Wv, Wo);
    gemm16_kernel<<<dim3(12, 64), 256, GEMM_SMEM>>>(nullptr, -1);
    attn_kernel<<<dim3(32, 16), 128, ATTN_SMEM>>>();
    gemm16_kernel<<<dim3(4, 64), 256, GEMM_SMEM>>>(out, 3);
}

// round 15
// speedup vs baseline: 1.1448x; 1.1448x over previous
#include <cuda_runtime.h>
#include <cuda_fp16.h>
#include <cstdint>

#define SS 4096
#define DK 64
#define DM 512
#define HH 8
#define BB 2
#define BH 16

// Scratch (static device globals — no runtime allocation)
__device__ __half g_Xh[BB*SS*DM];    // x converted to fp16 [m][k]
__device__ __half g_WT[4*DM*DM];     // Wq,Wk,Wv,Wo transposed to [n][k] fp16
__device__ __half g_Qh[BH*SS*DK];    // [bh][s][d], pre-scaled by log2(e)/8
__device__ __half g_Kh[BH*SS*DK];    // [bh][s][d]
__device__ __half g_Vh[BH*SS*DK];    // [bh][d][s]  (transposed for B-frag loads)
__device__ __half g_Oh[BB*SS*DM];    // attention output fp16 (concat layout)

__device__ __forceinline__ uint32_t pack_half2(float lo, float hi) {
    uint32_t u; asm("cvt.rn.f16x2.f32 %0, %1, %2;" : "=r"(u) : "f"(hi), "f"(lo)); return u;
}
__device__ __forceinline__ uint32_t ex2h2(uint32_t x) {
    uint32_t y; asm("ex2.approx.f16x2 %0, %1;" : "=r"(y) : "r"(x)); return y;
}
__device__ __forceinline__ uint32_t hadd2(uint32_t a, uint32_t b) {
    uint32_t y; asm("add.f16x2 %0, %1, %2;" : "=r"(y) : "r"(a), "r"(b)); return y;
}
// fp16: D += A(16x16) * B(16x8), f32 accum
__device__ __forceinline__ void mma16(float* d, const uint32_t* a, const uint32_t* b) {
    asm volatile("mma.sync.aligned.m16n8k16.row.col.f32.f16.f16.f32 "
        "{%0,%1,%2,%3}, {%4,%5,%6,%7}, {%8,%9}, {%0,%1,%2,%3};"
        : "+f"(d[0]), "+f"(d[1]), "+f"(d[2]), "+f"(d[3])
        : "r"(a[0]), "r"(a[1]), "r"(a[2]), "r"(a[3]), "r"(b[0]), "r"(b[1]));
}
__device__ __forceinline__ void cpa16(uint32_t dst, const void* src) {
    asm volatile("cp.async.cg.shared.global [%0], [%1], 16;" :: "r"(dst), "l"(src));
}
// 4x m8n8 b16 matrices -> mma B fragments
__device__ __forceinline__ void ldsm4(uint32_t& r0, uint32_t& r1, uint32_t& r2, uint32_t& r3,
                                      uint32_t addr) {
    asm volatile("ldmatrix.sync.aligned.m8n8.x4.shared.b16 {%0,%1,%2,%3}, [%4];"
        : "=r"(r0), "=r"(r1), "=r"(r2), "=r"(r3) : "r"(addr));
}

// ================= converters =================
__global__ __launch_bounds__(256) void convx_kernel(const float* __restrict__ X) {
    size_t i = ((size_t)blockIdx.x*256 + threadIdx.x) * 8;
    float4 v0 = *(const float4*)(X + i);
    float4 v1 = *(const float4*)(X + i + 4);
    uint4 p;
    p.x = pack_half2(v0.x, v0.y); p.y = pack_half2(v0.z, v0.w);
    p.z = pack_half2(v1.x, v1.y); p.w = pack_half2(v1.z, v1.w);
    *(uint4*)(g_Xh + i) = p;
}

// transpose+convert weights: g_WT[w][n][k] = W_w[k][n]
__global__ __launch_bounds__(256) void convw_kernel(const float* __restrict__ Wq,
                                                    const float* __restrict__ Wk,
                                                    const float* __restrict__ Wv,
                                                    const float* __restrict__ Wo) {
    __shared__ float t[32][33];
    const int w = blockIdx.z;
    const float* W = (w==0) ? Wq : (w==1) ? Wk : (w==2) ? Wv : Wo;
    __half* out = g_WT + (size_t)w*DM*DM;
    const int tx = threadIdx.x & 31, ty = threadIdx.x >> 5;
    const int bx = blockIdx.x * 32, by = blockIdx.y * 32;
    #pragma unroll
    for (int j = 0; j < 32; j += 8)
        t[ty+j][tx] = W[(size_t)(by+ty+j)*DM + bx+tx];
    __syncthreads();
    #pragma unroll
    for (int j = 0; j < 32; j += 8)
        out[(size_t)(bx+ty+j)*DM + by+tx] = __float2half_rn(t[tx][ty+j]);
}

// ================= fp16 GEMM: 128x128x32, 3-stage cp.async, 8 warps x (64x32) ===========
#define GBM 128
#define GBN 128
#define GBK 32
#define GAST 40
#define STG_A (GBM*GAST)
#define STG_H ((GBM+GBN)*GAST)
#define GSM_TOTAL (3*STG_H)           // 61440 bytes

// mode: -1 => qkv from g_Xh; 3 => oproj from g_Oh -> Out (fp32)
__global__ __launch_bounds__(256) void gemm16_kernel(float* __restrict__ Out, int mode)
{
    extern __shared__ __half gsm[];
    const int tid = threadIdx.x;
    const int warp = tid >> 5, lane = tid & 31;
    const int g = lane >> 2, c = lane & 3;
    const int wm = (warp & 1) * 64, wn = (warp >> 1) * 32;
    const int mb = blockIdx.y;

    int proj, cb;
    const __half* A;
    if (mode < 0) { proj = blockIdx.x >> 2; cb = (blockIdx.x & 3) * GBN; A = g_Xh; }
    else          { proj = 3;               cb = blockIdx.x * GBN;       A = g_Oh; }
    const __half* Bp = g_WT + (size_t)proj*DM*DM;

    float acc[4][4][4];
    #pragma unroll
    for (int i=0;i<4;i++)
        #pragma unroll
        for (int j=0;j<4;j++)
            #pragma unroll
            for (int k=0;k<4;k++) acc[i][j][k] = 0.f;

    uint32_t sb = (uint32_t)__cvta_generic_to_shared(gsm);
    const int ar = tid >> 1;
    const int ac = (tid & 1) * 2;

    const __half* Ag = A  + (size_t)(mb*GBM + ar)*DM;
    const __half* Bg = Bp + (size_t)(cb + ar)*DM;

    auto issue = [&](int slab, int stg) {
        uint32_t ab = sb + (uint32_t)(stg*STG_H)*2;
        uint32_t bb = ab + (uint32_t)STG_A*2;
        int k0 = slab * GBK;
        #pragma unroll
        for (int i = 0; i < 2; i++) {
            int ch = ac + i;
            cpa16(ab + (uint32_t)(ar*GAST + ch*8)*2, Ag + k0 + ch*8);
            cpa16(bb + (uint32_t)(ar*GAST + ch*8)*2, Bg + k0 + ch*8);
        }
        asm volatile("cp.async.commit_group;" ::: "memory");
    };

    issue(0, 0);
    issue(1, 1);

    const int NSLAB = DM / GBK;
    for (int slab = 0; slab < NSLAB; slab++) {
        const int stg = slab % 3;
        if (slab + 2 < NSLAB) {
            issue(slab + 2, (slab + 2) % 3);
            asm volatile("cp.async.wait_group 2;" ::: "memory");
        } else if (slab + 1 < NSLAB) {
            asm volatile("cp.async.wait_group 1;" ::: "memory");
        } else {
            asm volatile("cp.async.wait_group 0;" ::: "memory");
        }
        __syncthreads();

        const __half* As_ = gsm + stg*STG_H;
        const __half* Bs_ = As_ + STG_A;

        #pragma unroll
        for (int ks = 0; ks < 2; ks++) {
            uint32_t a[4][4];
            #pragma unroll
            for (int mi = 0; mi < 4; mi++) {
                const __half* ap = As_ + (wm + mi*16 + g)*GAST + ks*16 + 2*c;
                a[mi][0] = *(const uint32_t*)(ap);
                a[mi][1] = *(const uint32_t*)(ap + 8*GAST);
                a[mi][2] = *(const uint32_t*)(ap + 8);
                a[mi][3] = *(const uint32_t*)(ap + 8*GAST + 8);
            }
            #pragma unroll
            for (int ni = 0; ni < 4; ni++) {
                uint32_t b[2];
                const __half* bp = Bs_ + (wn + ni*8 + g)*GAST + ks*16 + 2*c;
                b[0] = *(const uint32_t*)(bp);
                b[1] = *(const uint32_t*)(bp + 8);
                #pragma unroll
                for (int mi = 0; mi < 4; mi++) mma16(acc[mi][ni], a[mi], b);
            }
        }
        __syncthreads();
    }

    if (proj == 3) {
        #pragma unroll
        for (int mi = 0; mi < 4; mi++)
            #pragma unroll
            for (int h = 0; h < 2; h++) {
                int gm = mb*GBM + wm + mi*16 + g + h*8;
                #pragma unroll
                for (int ni = 0; ni < 4; ni++) {
                    float2 v = { acc[mi][ni][h*2+0], acc[mi][ni][h*2+1] };
                    *(float2*)(Out + (size_t)gm*DM + cb + wn + ni*8 + 2*c) = v;
                }
            }
    } else {
        const float qscale = (proj == 0) ? 0.125f * 1.44269504088896f : 1.0f;
        #pragma unroll
        for (int mi = 0; mi < 4; mi++)
            #pragma unroll
            for (int h = 0; h < 2; h++) {
                int gm = mb*GBM + wm + mi*16 + g + h*8;
                int b = gm >> 12, s = gm & (SS-1);
                #pragma unroll
                for (int ni = 0; ni < 4; ni++) {
                    int wc = cb + wn + ni*8 + 2*c;
                    int hd = wc >> 6, d = wc & 63;
                    float v0 = acc[mi][ni][h*2+0];
                    float v1 = acc[mi][ni][h*2+1];
                    if (proj == 2) {
                        __half* o = g_Vh + ((size_t)(b*HH + hd)*DK + d)*SS + s;
                        o[0]  = __float2half_rn(v0);
                        o[SS] = __float2half_rn(v1);
                    } else {
                        __half* OutB = (proj == 0) ? g_Qh : g_Kh;
                        *(uint32_t*)(OutB + (((size_t)(b*HH + hd)*SS) + s)*DK + d)
                            = pack_half2(v0*qscale, v1*qscale);
                    }
                }
            }
    }
}

// ===== Flash attention v9: 8 warps x 16 rows, 4-deep buffers, 1 barrier per 2 tiles =====
#define KSTH 72                  // row stride in halves -> ldsm rows on banks 4r, conflict-free
#define TILE_H (64*KSTH)         // 4608 halves per buffer
#define SMH_TOTAL (8*TILE_H)     // K0..K3,V0..V3 = 36864 halves = 73728 bytes
#define NKT (SS/64)              // 64 key tiles

__global__ __launch_bounds__(256, 2) void attn_kernel()
{
    extern __shared__ __half smh[];
    const int tid = threadIdx.x;
    const int warp = tid >> 5, lane = tid & 31;
    const int g = lane >> 2, c = lane & 3;
    const int wm = warp * 16;
    const int qt = blockIdx.x;   // 0..31
    const int bh = blockIdx.y;   // 0..15

    const __half* Qg = g_Qh + ((size_t)bh*SS + qt*128)*DK;
    const __half* Kg = g_Kh + (size_t)bh*SS*DK;
    const __half* Vg = g_Vh + (size_t)bh*DK*SS;

    // stage Q through smem (uses K0/K1 buffer space), pull A-fragments into registers
    #pragma unroll
    for (int i = 0; i < 4; i++) {
        int e = tid + i*256;
        int row = e >> 3, ch = e & 7;
        *(uint4*)(smh + row*KSTH + ch*8) = *(const uint4*)(Qg + (size_t)row*DK + ch*8);
    }
    __syncthreads();
    uint32_t q[4][4];
    #pragma unroll
    for (int t = 0; t < 4; t++) {
        q[t][0] = *(const uint32_t*)(smh + (wm+g  )*KSTH + t*16 + 2*c);
        q[t][1] = *(const uint32_t*)(smh + (wm+g+8)*KSTH + t*16 + 2*c);
        q[t][2] = *(const uint32_t*)(smh + (wm+g  )*KSTH + t*16 + 2*c + 8);
        q[t][3] = *(const uint32_t*)(smh + (wm+g+8)*KSTH + t*16 + 2*c + 8);
    }
    __syncthreads();

    uint32_t sb = (uint32_t)__cvta_generic_to_shared(smh);
    const int l_row = tid >> 3, l_ch = tid & 7;

    // per-lane ldmatrix base offset (bytes)
    const uint32_t lmb = (uint32_t)((((lane >> 4) * 8 + (lane & 7)) * KSTH
                                    + ((lane >> 3) & 1) * 8) * 2);

    auto issue = [&](int kt) {
        uint32_t kdst = sb + (uint32_t)((kt & 3)*TILE_H)*2;
        uint32_t vdst = sb + (uint32_t)((4 + (kt & 3))*TILE_H)*2;
        #pragma unroll
        for (int i = 0; i < 2; i++) {
            int row = l_row + i*32;
            cpa16(kdst + (uint32_t)(row*KSTH + l_ch*8)*2,
                  Kg + (size_t)(kt*64 + row)*DK + l_ch*8);
            cpa16(vdst + (uint32_t)(row*KSTH + l_ch*8)*2,
                  Vg + (size_t)row*SS + kt*64 + l_ch*8);
        }
        asm volatile("cp.async.commit_group;" ::: "memory");
    };

    // prologue: fill all 4 buffers
    issue(0); issue(1); issue(2); issue(3);

    float o[8][4];
    float lr[2] = {0.f, 0.f};
    #pragma unroll
    for (int n=0;n<8;n++)
        #pragma unroll
        for (int k=0;k<4;k++) o[n][k]=0.f;

    asm volatile("cp.async.wait_group 2;" ::: "memory");   // tiles 0,1 ready
    __syncthreads();

    // process one 64-key tile (S -> exp -> PV)
    auto tile = [&](int kt) {
        const uint32_t kbase = sb + (uint32_t)((kt & 3)*TILE_H)*2 + lmb;
        const uint32_t vbase = sb + (uint32_t)((4 + (kt & 3))*TILE_H)*2 + lmb;

        float s[8][4];
        #pragma unroll
        for (int n=0;n<8;n++)
            #pragma unroll
            for (int k=0;k<4;k++) s[n][k] = 0.f;

        #pragma unroll
        for (int t = 0; t < 4; t++)
            #pragma unroll
            for (int j = 0; j < 4; j++) {
                uint32_t b[4];
                ldsm4(b[0], b[1], b[2], b[3], kbase + (uint32_t)((j*16*KSTH + t*16) * 2));
                mma16(s[2*j  ], q[t], b);
                mma16(s[2*j+1], q[t], b + 2);
            }

        uint32_t ph[8][2];
        #pragma unroll
        for (int n = 0; n < 8; n++) {
            ph[n][0] = ex2h2(pack_half2(s[n][0], s[n][1]));
            ph[n][1] = ex2h2(pack_half2(s[n][2], s[n][3]));
        }
        #pragma unroll
        for (int h = 0; h < 2; h++) {
            uint32_t t0 = hadd2(ph[0][h], ph[1][h]);
            uint32_t t1 = hadd2(ph[2][h], ph[3][h]);
            uint32_t t2 = hadd2(ph[4][h], ph[5][h]);
            uint32_t t3 = hadd2(ph[6][h], ph[7][h]);
            uint32_t t4 = hadd2(t0, t1);
            uint32_t t5 = hadd2(t2, t3);
            float2 f0 = __half22float2(*(__half2*)&t4);
            float2 f1 = __half22float2(*(__half2*)&t5);
            lr[h] += (f0.x + f0.y) + (f1.x + f1.y);
        }

        #pragma unroll
        for (int t = 0; t < 4; t++) {
            uint32_t a[4];
            a[0] = ph[2*t  ][0];
            a[1] = ph[2*t  ][1];
            a[2] = ph[2*t+1][0];
            a[3] = ph[2*t+1][1];
            #pragma unroll
            for (int j = 0; j < 4; j++) {
                uint32_t b[4];
                ldsm4(b[0], b[1], b[2], b[3], vbase + (uint32_t)((j*16*KSTH + t*16) * 2));
                mma16(o[2*j  ], a, b);
                mma16(o[2*j+1], a, b + 2);
            }
        }
    };

    // main loop: 2 tiles per barrier; warps free-run within the pair
    for (int kt = 0; kt < NKT; kt += 2) {
        if (kt + 3 < NKT) {
            issue(kt + 2);           // buffer (kt+2)&3 — readers done before last barrier
            issue(kt + 3);
            asm volatile("cp.async.wait_group 2;" ::: "memory");  // kt, kt+1 landed
        } else if (kt + 2 < NKT) {
            issue(kt + 2);
            asm volatile("cp.async.wait_group 1;" ::: "memory");
        } else {
            asm volatile("cp.async.wait_group 0;" ::: "memory");
        }
        tile(kt);
        tile(kt + 1);
        __syncthreads();             // retire buffers (kt,kt+1) before next body overwrites
    }

    // lane-group reduction of row sums
    #pragma unroll
    for (int h = 0; h < 2; h++) {
        lr[h] += __shfl_xor_sync(0xffffffffu, lr[h], 1);
        lr[h] += __shfl_xor_sync(0xffffffffu, lr[h], 2);
    }

    // finalize: normalize, write fp16 concat layout [b][s][h*64+d]
    const int b = bh >> 3, hd = bh & 7;
    #pragma unroll
    for (int h = 0; h < 2; h++) {
        float inv = 1.f / lr[h];
        int row = qt*128 + wm + g + h*8;
        __half* op = g_Oh + ((size_t)(b*SS + row))*DM + hd*DK;
        #pragma unroll
        for (int n=0;n<8;n++)
            *(uint32_t*)(op + n*8 + 2*c) = pack_half2(o[n][h*2]*inv, o[n][h*2+1]*inv);
    }
}

extern "C" void kernel_launch(void* const* d_in, const int* in_sizes, int n_in,
                              void* d_out, int out_size) {
    const float* x  = (const float*)d_in[0];
    const float* Wq = (const float*)d_in[1];
    const float* Wk = (const float*)d_in[2];
    const float* Wv = (const float*)d_in[3];
    const float* Wo = (const float*)d_in[4];
    float* out = (float*)d_out;
    (void)in_sizes; (void)n_in; (void)out_size;

    static const int GEMM_SMEM = GSM_TOTAL * 2;  // 61440 bytes
    static const int ATTN_SMEM = SMH_TOTAL * 2;  // 73728 bytes
    cudaFuncSetAttribute(gemm16_kernel, cudaFuncAttributeMaxDynamicSharedMemorySize, GEMM_SMEM);
    cudaFuncSetAttribute(attn_kernel, cudaFuncAttributeMaxDynamicSharedMemorySize, ATTN_SMEM);

    convx_kernel<<<2048, 256>>>(x);
    convw_kernel<<<dim3(16, 16, 4), 256>>>(Wq, Wk, Wv, Wo);
    gemm16_kernel<<<dim3(12, 64), 256, GEMM_SMEM>>>(nullptr, -1);
    attn_kernel<<<dim3(32, 16), 256, ATTN_SMEM>>>();
    gemm16_kernel<<<dim3(4, 64), 256, GEMM_SMEM>>>(out, 3);
}

// round 17
// speedup vs baseline: 1.1501x; 1.0047x over previous
#include <cuda_runtime.h>
#include <cuda_fp16.h>
#include <cstdint>

#define SS 4096
#define DK 64
#define DM 512
#define HH 8
#define BB 2
#define BH 16

// Scratch (static device globals — no runtime allocation)
__device__ __half g_Xh[BB*SS*DM];    // x converted to fp16 [m][k]
__device__ __half g_WT[4*DM*DM];     // Wq,Wk,Wv,Wo transposed to [n][k] fp16
__device__ __half g_Qh[BH*SS*DK];    // [bh][s][d], pre-scaled by log2(e)/8
__device__ __half g_Kh[BH*SS*DK];    // [bh][s][d]
__device__ __half g_Vh[BH*SS*DK];    // [bh][d][s]  (transposed for B-frag loads)
__device__ __half g_Oh[BB*SS*DM];    // attention output fp16 (concat layout)

__device__ __forceinline__ uint32_t pack_half2(float lo, float hi) {
    uint32_t u; asm("cvt.rn.f16x2.f32 %0, %1, %2;" : "=r"(u) : "f"(hi), "f"(lo)); return u;
}
__device__ __forceinline__ uint32_t ex2h2(uint32_t x) {
    uint32_t y; asm("ex2.approx.f16x2 %0, %1;" : "=r"(y) : "r"(x)); return y;
}
__device__ __forceinline__ uint32_t hadd2(uint32_t a, uint32_t b) {
    uint32_t y; asm("add.f16x2 %0, %1, %2;" : "=r"(y) : "r"(a), "r"(b)); return y;
}
// fp16: D += A(16x16) * B(16x8), f32 accum
__device__ __forceinline__ void mma16(float* d, const uint32_t* a, const uint32_t* b) {
    asm volatile("mma.sync.aligned.m16n8k16.row.col.f32.f16.f16.f32 "
        "{%0,%1,%2,%3}, {%4,%5,%6,%7}, {%8,%9}, {%0,%1,%2,%3};"
        : "+f"(d[0]), "+f"(d[1]), "+f"(d[2]), "+f"(d[3])
        : "r"(a[0]), "r"(a[1]), "r"(a[2]), "r"(a[3]), "r"(b[0]), "r"(b[1]));
}
__device__ __forceinline__ void cpa16(uint32_t dst, const void* src) {
    asm volatile("cp.async.cg.shared.global [%0], [%1], 16;" :: "r"(dst), "l"(src));
}
// 4x m8n8 b16 matrices -> mma B fragments
__device__ __forceinline__ void ldsm4(uint32_t& r0, uint32_t& r1, uint32_t& r2, uint32_t& r3,
                                      uint32_t addr) {
    asm volatile("ldmatrix.sync.aligned.m8n8.x4.shared.b16 {%0,%1,%2,%3}, [%4];"
        : "=r"(r0), "=r"(r1), "=r"(r2), "=r"(r3) : "r"(addr));
}

// ========== merged converter: blocks [0,2048) convert x; [2048,3072) transpose weights ====
__global__ __launch_bounds__(256) void conv_kernel(const float* __restrict__ X,
                                                   const float* __restrict__ Wq,
                                                   const float* __restrict__ Wk,
                                                   const float* __restrict__ Wv,
                                                   const float* __restrict__ Wo) {
    __shared__ float t[32][33];
    const int bid = blockIdx.x;
    if (bid < 2048) {
        size_t i = ((size_t)bid*256 + threadIdx.x) * 8;
        float4 v0 = *(const float4*)(X + i);
        float4 v1 = *(const float4*)(X + i + 4);
        uint4 p;
        p.x = pack_half2(v0.x, v0.y); p.y = pack_half2(v0.z, v0.w);
        p.z = pack_half2(v1.x, v1.y); p.w = pack_half2(v1.z, v1.w);
        *(uint4*)(g_Xh + i) = p;
        return;
    }
    const int id2 = bid - 2048;          // 0..1023
    const int w = id2 >> 8;              // 0..3
    const int rem = id2 & 255;
    const int bx = (rem & 15) * 32;      // n block
    const int by = (rem >> 4) * 32;      // k block
    const float* W = (w==0) ? Wq : (w==1) ? Wk : (w==2) ? Wv : Wo;
    __half* out = g_WT + (size_t)w*DM*DM;
    const int tx = threadIdx.x & 31, ty = threadIdx.x >> 5;
    #pragma unroll
    for (int j = 0; j < 32; j += 8)
        t[ty+j][tx] = W[(size_t)(by+ty+j)*DM + bx+tx];
    __syncthreads();
    #pragma unroll
    for (int j = 0; j < 32; j += 8)
        out[(size_t)(bx+ty+j)*DM + by+tx] = __float2half_rn(t[tx][ty+j]);
}

// ================= fp16 GEMM: 128x128x32, 3-stage cp.async, 8 warps x (64x32) ===========
#define GBM 128
#define GBN 128
#define GBK 32
#define GAST 40
#define STG_A (GBM*GAST)
#define STG_H ((GBM+GBN)*GAST)
#define GSM_TOTAL (3*STG_H)           // 61440 bytes

// mode: -1 => qkv from g_Xh; 3 => oproj from g_Oh -> Out (fp32)
__global__ __launch_bounds__(256) void gemm16_kernel(float* __restrict__ Out, int mode)
{
    extern __shared__ __half gsm[];
    const int tid = threadIdx.x;
    const int warp = tid >> 5, lane = tid & 31;
    const int g = lane >> 2, c = lane & 3;
    const int wm = (warp & 1) * 64, wn = (warp >> 1) * 32;
    const int mb = blockIdx.y;

    int proj, cb;
    const __half* A;
    if (mode < 0) { proj = blockIdx.x >> 2; cb = (blockIdx.x & 3) * GBN; A = g_Xh; }
    else          { proj = 3;               cb = blockIdx.x * GBN;       A = g_Oh; }
    const __half* Bp = g_WT + (size_t)proj*DM*DM;

    float acc[4][4][4];
    #pragma unroll
    for (int i=0;i<4;i++)
        #pragma unroll
        for (int j=0;j<4;j++)
            #pragma unroll
            for (int k=0;k<4;k++) acc[i][j][k] = 0.f;

    uint32_t sb = (uint32_t)__cvta_generic_to_shared(gsm);
    const int ar = tid >> 1;
    const int ac = (tid & 1) * 2;

    const __half* Ag = A  + (size_t)(mb*GBM + ar)*DM;
    const __half* Bg = Bp + (size_t)(cb + ar)*DM;

    auto issue = [&](int slab, int stg) {
        uint32_t ab = sb + (uint32_t)(stg*STG_H)*2;
        uint32_t bb = ab + (uint32_t)STG_A*2;
        int k0 = slab * GBK;
        #pragma unroll
        for (int i = 0; i < 2; i++) {
            int ch = ac + i;
            cpa16(ab + (uint32_t)(ar*GAST + ch*8)*2, Ag + k0 + ch*8);
            cpa16(bb + (uint32_t)(ar*GAST + ch*8)*2, Bg + k0 + ch*8);
        }
        asm volatile("cp.async.commit_group;" ::: "memory");
    };

    issue(0, 0);
    issue(1, 1);

    const int NSLAB = DM / GBK;
    for (int slab = 0; slab < NSLAB; slab++) {
        const int stg = slab % 3;
        if (slab + 2 < NSLAB) {
            issue(slab + 2, (slab + 2) % 3);
            asm volatile("cp.async.wait_group 2;" ::: "memory");
        } else if (slab + 1 < NSLAB) {
            asm volatile("cp.async.wait_group 1;" ::: "memory");
        } else {
            asm volatile("cp.async.wait_group 0;" ::: "memory");
        }
        __syncthreads();

        const __half* As_ = gsm + stg*STG_H;
        const __half* Bs_ = As_ + STG_A;

        #pragma unroll
        for (int ks = 0; ks < 2; ks++) {
            uint32_t a[4][4];
            #pragma unroll
            for (int mi = 0; mi < 4; mi++) {
                const __half* ap = As_ + (wm + mi*16 + g)*GAST + ks*16 + 2*c;
                a[mi][0] = *(const uint32_t*)(ap);
                a[mi][1] = *(const uint32_t*)(ap + 8*GAST);
                a[mi][2] = *(const uint32_t*)(ap + 8);
                a[mi][3] = *(const uint32_t*)(ap + 8*GAST + 8);
            }
            #pragma unroll
            for (int ni = 0; ni < 4; ni++) {
                uint32_t b[2];
                const __half* bp = Bs_ + (wn + ni*8 + g)*GAST + ks*16 + 2*c;
                b[0] = *(const uint32_t*)(bp);
                b[1] = *(const uint32_t*)(bp + 8);
                #pragma unroll
                for (int mi = 0; mi < 4; mi++) mma16(acc[mi][ni], a[mi], b);
            }
        }
        __syncthreads();
    }

    if (proj == 3) {
        #pragma unroll
        for (int mi = 0; mi < 4; mi++)
            #pragma unroll
            for (int h = 0; h < 2; h++) {
                int gm = mb*GBM + wm + mi*16 + g + h*8;
                #pragma unroll
                for (int ni = 0; ni < 4; ni++) {
                    float2 v = { acc[mi][ni][h*2+0], acc[mi][ni][h*2+1] };
                    *(float2*)(Out + (size_t)gm*DM + cb + wn + ni*8 + 2*c) = v;
                }
            }
    } else {
        const float qscale = (proj == 0) ? 0.125f * 1.44269504088896f : 1.0f;
        #pragma unroll
        for (int mi = 0; mi < 4; mi++)
            #pragma unroll
            for (int h = 0; h < 2; h++) {
                int gm = mb*GBM + wm + mi*16 + g + h*8;
                int b = gm >> 12, s = gm & (SS-1);
                #pragma unroll
                for (int ni = 0; ni < 4; ni++) {
                    int wc = cb + wn + ni*8 + 2*c;
                    int hd = wc >> 6, d = wc & 63;
                    float v0 = acc[mi][ni][h*2+0];
                    float v1 = acc[mi][ni][h*2+1];
                    if (proj == 2) {
                        __half* o = g_Vh + ((size_t)(b*HH + hd)*DK + d)*SS + s;
                        o[0]  = __float2half_rn(v0);
                        o[SS] = __float2half_rn(v1);
                    } else {
                        __half* OutB = (proj == 0) ? g_Qh : g_Kh;
                        *(uint32_t*)(OutB + (((size_t)(b*HH + hd)*SS) + s)*DK + d)
                            = pack_half2(v0*qscale, v1*qscale);
                    }
                }
            }
    }
}

// ===== Flash attention v9: 8 warps x 16 rows, 4-deep buffers, 1 barrier per 2 tiles =====
#define KSTH 72                  // row stride in halves -> ldsm rows on banks 4r, conflict-free
#define TILE_H (64*KSTH)         // 4608 halves per buffer
#define SMH_TOTAL (8*TILE_H)     // K0..K3,V0..V3 = 36864 halves = 73728 bytes
#define NKT (SS/64)              // 64 key tiles

__global__ __launch_bounds__(256, 2) void attn_kernel()
{
    extern __shared__ __half smh[];
    const int tid = threadIdx.x;
    const int warp = tid >> 5, lane = tid & 31;
    const int g = lane >> 2, c = lane & 3;
    const int wm = warp * 16;
    const int qt = blockIdx.x;   // 0..31
    const int bh = blockIdx.y;   // 0..15

    const __half* Qg = g_Qh + ((size_t)bh*SS + qt*128)*DK;
    const __half* Kg = g_Kh + (size_t)bh*SS*DK;
    const __half* Vg = g_Vh + (size_t)bh*DK*SS;

    // stage Q through smem (uses K0/K1 buffer space), pull A-fragments into registers
    #pragma unroll
    for (int i = 0; i < 4; i++) {
        int e = tid + i*256;
        int row = e >> 3, ch = e & 7;
        *(uint4*)(smh + row*KSTH + ch*8) = *(const uint4*)(Qg + (size_t)row*DK + ch*8);
    }
    __syncthreads();
    uint32_t q[4][4];
    #pragma unroll
    for (int t = 0; t < 4; t++) {
        q[t][0] = *(const uint32_t*)(smh + (wm+g  )*KSTH + t*16 + 2*c);
        q[t][1] = *(const uint32_t*)(smh + (wm+g+8)*KSTH + t*16 + 2*c);
        q[t][2] = *(const uint32_t*)(smh + (wm+g  )*KSTH + t*16 + 2*c + 8);
        q[t][3] = *(const uint32_t*)(smh + (wm+g+8)*KSTH + t*16 + 2*c + 8);
    }
    __syncthreads();

    uint32_t sb = (uint32_t)__cvta_generic_to_shared(smh);
    const int l_row = tid >> 3, l_ch = tid & 7;

    // per-lane ldmatrix base offset (bytes)
    const uint32_t lmb = (uint32_t)((((lane >> 4) * 8 + (lane & 7)) * KSTH
                                    + ((lane >> 3) & 1) * 8) * 2);

    auto issue = [&](int kt) {
        uint32_t kdst = sb + (uint32_t)((kt & 3)*TILE_H)*2;
        uint32_t vdst = sb + (uint32_t)((4 + (kt & 3))*TILE_H)*2;
        #pragma unroll
        for (int i = 0; i < 2; i++) {
            int row = l_row + i*32;
            cpa16(kdst + (uint32_t)(row*KSTH + l_ch*8)*2,
                  Kg + (size_t)(kt*64 + row)*DK + l_ch*8);
            cpa16(vdst + (uint32_t)(row*KSTH + l_ch*8)*2,
                  Vg + (size_t)row*SS + kt*64 + l_ch*8);
        }
        asm volatile("cp.async.commit_group;" ::: "memory");
    };

    // prologue: fill all 4 buffers
    issue(0); issue(1); issue(2); issue(3);

    float o[8][4];
    float lr[2] = {0.f, 0.f};
    #pragma unroll
    for (int n=0;n<8;n++)
        #pragma unroll
        for (int k=0;k<4;k++) o[n][k]=0.f;

    asm volatile("cp.async.wait_group 2;" ::: "memory");   // tiles 0,1 ready
    __syncthreads();

    // process one 64-key tile (S -> exp -> PV)
    auto tile = [&](int kt) {
        const uint32_t kbase = sb + (uint32_t)((kt & 3)*TILE_H)*2 + lmb;
        const uint32_t vbase = sb + (uint32_t)((4 + (kt & 3))*TILE_H)*2 + lmb;

        float s[8][4];
        #pragma unroll
        for (int n=0;n<8;n++)
            #pragma unroll
            for (int k=0;k<4;k++) s[n][k] = 0.f;

        #pragma unroll
        for (int t = 0; t < 4; t++)
            #pragma unroll
            for (int j = 0; j < 4; j++) {
                uint32_t b[4];
                ldsm4(b[0], b[1], b[2], b[3], kbase + (uint32_t)((j*16*KSTH + t*16) * 2));
                mma16(s[2*j  ], q[t], b);
                mma16(s[2*j+1], q[t], b + 2);
            }

        uint32_t ph[8][2];
        #pragma unroll
        for (int n = 0; n < 8; n++) {
            ph[n][0] = ex2h2(pack_half2(s[n][0], s[n][1]));
            ph[n][1] = ex2h2(pack_half2(s[n][2], s[n][3]));
        }
        #pragma unroll
        for (int h = 0; h < 2; h++) {
            uint32_t t0 = hadd2(ph[0][h], ph[1][h]);
            uint32_t t1 = hadd2(ph[2][h], ph[3][h]);
            uint32_t t2 = hadd2(ph[4][h], ph[5][h]);
            uint32_t t3 = hadd2(ph[6][h], ph[7][h]);
            uint32_t t4 = hadd2(t0, t1);
            uint32_t t5 = hadd2(t2, t3);
            float2 f0 = __half22float2(*(__half2*)&t4);
            float2 f1 = __half22float2(*(__half2*)&t5);
            lr[h] += (f0.x + f0.y) + (f1.x + f1.y);
        }

        #pragma unroll
        for (int t = 0; t < 4; t++) {
            uint32_t a[4];
            a[0] = ph[2*t  ][0];
            a[1] = ph[2*t  ][1];
            a[2] = ph[2*t+1][0];
            a[3] = ph[2*t+1][1];
            #pragma unroll
            for (int j = 0; j < 4; j++) {
                uint32_t b[4];
                ldsm4(b[0], b[1], b[2], b[3], vbase + (uint32_t)((j*16*KSTH + t*16) * 2));
                mma16(o[2*j  ], a, b);
                mma16(o[2*j+1], a, b + 2);
            }
        }
    };

    // main loop: 2 tiles per barrier; warps free-run within the pair
    for (int kt = 0; kt < NKT; kt += 2) {
        if (kt + 3 < NKT) {
            issue(kt + 2);           // buffer (kt+2)&3 — readers done before last barrier
            issue(kt + 3);
            asm volatile("cp.async.wait_group 2;" ::: "memory");  // kt, kt+1 landed
        } else if (kt + 2 < NKT) {
            issue(kt + 2);
            asm volatile("cp.async.wait_group 1;" ::: "memory");
        } else {
            asm volatile("cp.async.wait_group 0;" ::: "memory");
        }
        tile(kt);
        tile(kt + 1);
        __syncthreads();             // retire buffers (kt,kt+1) before next body overwrites
    }

    // lane-group reduction of row sums
    #pragma unroll
    for (int h = 0; h < 2; h++) {
        lr[h] += __shfl_xor_sync(0xffffffffu, lr[h], 1);
        lr[h] += __shfl_xor_sync(0xffffffffu, lr[h], 2);
    }

    // finalize: normalize, write fp16 concat layout [b][s][h*64+d]
    const int b = bh >> 3, hd = bh & 7;
    #pragma unroll
    for (int h = 0; h < 2; h++) {
        float inv = 1.f / lr[h];
        int row = qt*128 + wm + g + h*8;
        __half* op = g_Oh + ((size_t)(b*SS + row))*DM + hd*DK;
        #pragma unroll
        for (int n=0;n<8;n++)
            *(uint32_t*)(op + n*8 + 2*c) = pack_half2(o[n][h*2]*inv, o[n][h*2+1]*inv);
    }
}

extern "C" void kernel_launch(void* const* d_in, const int* in_sizes, int n_in,
                              void* d_out, int out_size) {
    const float* x  = (const float*)d_in[0];
    const float* Wq = (const float*)d_in[1];
    const float* Wk = (const float*)d_in[2];
    const float* Wv = (const float*)d_in[3];
    const float* Wo = (const float*)d_in[4];
    float* out = (float*)d_out;
    (void)in_sizes; (void)n_in; (void)out_size;

    static const int GEMM_SMEM = GSM_TOTAL * 2;  // 61440 bytes
    static const int ATTN_SMEM = SMH_TOTAL * 2;  // 73728 bytes
    cudaFuncSetAttribute(gemm16_kernel, cudaFuncAttributeMaxDynamicSharedMemorySize, GEMM_SMEM);
    cudaFuncSetAttribute(attn_kernel, cudaFuncAttributeMaxDynamicSharedMemorySize, ATTN_SMEM);

    conv_kernel<<<3072, 256>>>(x, Wq, Wk, Wv, Wo);
    gemm16_kernel<<<dim3(12, 64), 256, GEMM_SMEM>>>(nullptr, -1);
    attn_kernel<<<dim3(32, 16), 256, ATTN_SMEM>>>();
    gemm16_kernel<<<dim3(4, 64), 256, GEMM_SMEM>>>(out, 3);
}